// round 14
// baseline (speedup 1.0000x reference)
#include <cuda_runtime.h>
#include <cuda_bf16.h>
#include <cuda_fp16.h>
#include <math.h>

// ---------------- problem constants ----------------
#define BATCH 128
#define CCH   512
#define SS    121      // 11*11
#define SDIM  11
#define KK    9        // 3*3
#define C2    1024     // 2*C
#define CR    32       // C/SIGMA
#define OUT0  (BATCH*CCH*SS)

// ---------------- scratch (device globals; no allocation) ----------------
__device__ float g_A1[(size_t)BATCH * C2 * SS];
__device__ float g_asum[C2 * SS];
__device__ float g_acc1[C2 * SS];
__device__ float g_acc2[CCH * SS];
__device__ float g_task[CCH * SS];
__device__ float g_sk[BATCH * SS * KK];
__device__ float g_skraw[BATCH * SS * KK];
__device__ float g_skt[SS * KK];
__device__ float g_sktraw[SS * KK];
__device__ float g_y[BATCH * CCH];
__device__ float g_yt[CCH];
__device__ float g_ck[(size_t)BATCH * CCH * KK];
__device__ float g_ckt[CCH * KK];

// ---------------- bf16 split helpers (3-term path, lo-chain) ----------------
__device__ __forceinline__ void split_pack(float a, float b, unsigned& hi, unsigned& lo) {
    __nv_bfloat162 h = __float22bfloat162_rn(make_float2(a, b));
    float ra = a - __bfloat162float(h.x);
    float rb = b - __bfloat162float(h.y);
    __nv_bfloat162 l = __float22bfloat162_rn(make_float2(ra, rb));
    hi = *(unsigned*)&h;
    lo = *(unsigned*)&l;
}

__device__ __forceinline__ void mma_bf16(float c[4], const unsigned a[4], const unsigned b[2]) {
    asm volatile(
        "mma.sync.aligned.m16n8k16.row.col.f32.bf16.bf16.f32 "
        "{%0,%1,%2,%3}, {%4,%5,%6,%7}, {%8,%9}, {%0,%1,%2,%3};"
        : "+f"(c[0]), "+f"(c[1]), "+f"(c[2]), "+f"(c[3])
        : "r"(a[0]), "r"(a[1]), "r"(a[2]), "r"(a[3]), "r"(b[0]), "r"(b[1]));
}

// ---------------- fp16 split helpers (2-term path, big GEMMs) ----------------
__device__ __forceinline__ void split_pack_h(float a, float b, unsigned& hi, unsigned& lo) {
    __half2 h = __float22half2_rn(make_float2(a, b));
    float2 hf = __half22float2(h);
    __half2 l = __float22half2_rn(make_float2(a - hf.x, b - hf.y));
    hi = *(unsigned*)&h;
    lo = *(unsigned*)&l;
}
__device__ __forceinline__ unsigned pack_h(float a, float b) {
    __half2 h = __float22half2_rn(make_float2(a, b));
    return *(unsigned*)&h;
}

__device__ __forceinline__ void mma_f16(float c[4], const unsigned a[4], const unsigned b[2]) {
    asm volatile(
        "mma.sync.aligned.m16n8k16.row.col.f32.f16.f16.f32 "
        "{%0,%1,%2,%3}, {%4,%5,%6,%7}, {%8,%9}, {%0,%1,%2,%3};"
        : "+f"(c[0]), "+f"(c[1]), "+f"(c[2]), "+f"(c[3])
        : "r"(a[0]), "r"(a[1]), "r"(a[2]), "r"(a[3]), "r"(b[0]), "r"(b[1]));
}

#define BM 128
#define MT 8
#define NT 16

// ================= FP16 2-term GEMM: A = {hi,lo} planes, B = hi only =================
// O = act((W@X + bias) * gamma/sqrt(1+eps) + beta)
// MODE 0: BN+relu store; MODE 1: BN+relu atomicAdd (batch reduce)
template<int MODE>
__global__ __launch_bounds__(256) void tgemm_h(
    const float* __restrict__ W, const float* __restrict__ X,
    const float* __restrict__ bias, const float* __restrict__ gamma,
    const float* __restrict__ beta, float* __restrict__ out,
    int Kd, int P, long long strideX, long long strideO)
{
    __shared__ __align__(16) unsigned Asm[2][2][MT][32][4];
    __shared__ __align__(16) unsigned Bsm[2][NT][32][2];

    const float rsc = rsqrtf(1.f + 1e-5f);
    const float* Xb = X + (long long)blockIdx.z * strideX;
    float* Ob = out + (long long)blockIdx.z * strideO;
    const int row0 = blockIdx.y * BM;

    const int tid = threadIdx.x, lane = tid & 31, warp = tid >> 5;
    const int g = lane >> 2, tg = lane & 3;
    const int wm = warp >> 2;   // 0..1
    const int wn = warp & 3;    // 0..3

    float acc[4][4][4];
#pragma unroll
    for (int i = 0; i < 4; i++)
#pragma unroll
        for (int j = 0; j < 4; j++)
#pragma unroll
            for (int e = 0; e < 4; e++) acc[i][j][e] = 0.f;

    const int nt_iters = Kd / 16;

    // ---- prologue: stage 0 ----
    {
        const float* wr = W + (long long)(row0 + warp * 16 + g) * Kd + 2 * tg;
        float2 v00 = *(const float2*)wr;
        float2 v10 = *(const float2*)(wr + 8 * Kd);
        float2 v01 = *(const float2*)(wr + 8);
        float2 v11 = *(const float2*)(wr + 8 * Kd + 8);
        unsigned h, l;
        split_pack_h(v00.x, v00.y, h, l); Asm[0][0][warp][lane][0] = h; Asm[0][1][warp][lane][0] = l;
        split_pack_h(v10.x, v10.y, h, l); Asm[0][0][warp][lane][1] = h; Asm[0][1][warp][lane][1] = l;
        split_pack_h(v01.x, v01.y, h, l); Asm[0][0][warp][lane][2] = h; Asm[0][1][warp][lane][2] = l;
        split_pack_h(v11.x, v11.y, h, l); Asm[0][0][warp][lane][3] = h; Asm[0][1][warp][lane][3] = l;
#pragma unroll
        for (int q = 0; q < 2; q++) {
            int nt = warp * 2 + q;
            int p = nt * 8 + g;
            float b0a = 0.f, b0b = 0.f, b1a = 0.f, b1b = 0.f;
            if (p < P) {
                int k0 = 2 * tg;
                b0a = Xb[(long long)k0 * P + p];
                b0b = Xb[(long long)(k0 + 1) * P + p];
                b1a = Xb[(long long)(k0 + 8) * P + p];
                b1b = Xb[(long long)(k0 + 9) * P + p];
            }
            Bsm[0][nt][lane][0] = pack_h(b0a, b0b);
            Bsm[0][nt][lane][1] = pack_h(b1a, b1b);
        }
    }
    __syncthreads();

    for (int t = 0; t < nt_iters; t++) {
        const int cur = t & 1;
        const bool has_next = (t + 1 < nt_iters);
        float2 v00, v01, v10, v11;
        float xv0[2][2], xv1[2][2];
        if (has_next) {
            const int k = (t + 1) * 16;
            const float* wr = W + (long long)(row0 + warp * 16 + g) * Kd + k + 2 * tg;
            v00 = *(const float2*)wr;
            v10 = *(const float2*)(wr + 8 * Kd);
            v01 = *(const float2*)(wr + 8);
            v11 = *(const float2*)(wr + 8 * Kd + 8);
#pragma unroll
            for (int q = 0; q < 2; q++) {
                int nt = warp * 2 + q;
                int p = nt * 8 + g;
                xv0[q][0] = 0.f; xv0[q][1] = 0.f; xv1[q][0] = 0.f; xv1[q][1] = 0.f;
                if (p < P) {
                    int k0 = k + 2 * tg;
                    xv0[q][0] = Xb[(long long)k0 * P + p];
                    xv0[q][1] = Xb[(long long)(k0 + 1) * P + p];
                    xv1[q][0] = Xb[(long long)(k0 + 8) * P + p];
                    xv1[q][1] = Xb[(long long)(k0 + 9) * P + p];
                }
            }
        }

        unsigned aF[2][4][4], bF[4][2];
#pragma unroll
        for (int s = 0; s < 2; s++)
#pragma unroll
            for (int i = 0; i < 4; i++) {
                uint4 a4 = *(const uint4*)&Asm[cur][s][wm * 4 + i][lane][0];
                aF[s][i][0] = a4.x; aF[s][i][1] = a4.y; aF[s][i][2] = a4.z; aF[s][i][3] = a4.w;
            }
#pragma unroll
        for (int j = 0; j < 4; j++) {
            uint2 b2 = *(const uint2*)&Bsm[cur][wn * 4 + j][lane][0];
            bF[j][0] = b2.x; bF[j][1] = b2.y;
        }

        // 2-term: hi*hi + lo*hi
#pragma unroll
        for (int i = 0; i < 4; i++)
#pragma unroll
            for (int j = 0; j < 4; j++) {
                mma_f16(acc[i][j], aF[0][i], bF[j]);
                mma_f16(acc[i][j], aF[1][i], bF[j]);
            }

        if (has_next) {
            const int nb = cur ^ 1;
            unsigned h, l;
            split_pack_h(v00.x, v00.y, h, l); Asm[nb][0][warp][lane][0] = h; Asm[nb][1][warp][lane][0] = l;
            split_pack_h(v10.x, v10.y, h, l); Asm[nb][0][warp][lane][1] = h; Asm[nb][1][warp][lane][1] = l;
            split_pack_h(v01.x, v01.y, h, l); Asm[nb][0][warp][lane][2] = h; Asm[nb][1][warp][lane][2] = l;
            split_pack_h(v11.x, v11.y, h, l); Asm[nb][0][warp][lane][3] = h; Asm[nb][1][warp][lane][3] = l;
#pragma unroll
            for (int q = 0; q < 2; q++) {
                int nt = warp * 2 + q;
                Bsm[nb][nt][lane][0] = pack_h(xv0[q][0], xv0[q][1]);
                Bsm[nb][nt][lane][1] = pack_h(xv1[q][0], xv1[q][1]);
            }
            __syncthreads();
        }
    }

    // ---- epilogue ----
#pragma unroll
    for (int i = 0; i < 4; i++) {
        int r0 = row0 + (wm * 4 + i) * 16 + g;
#pragma unroll
        for (int half = 0; half < 2; half++) {
            int r = r0 + half * 8;
            float sc = gamma[r] * rsc, sh = beta[r], bi = bias[r];
#pragma unroll
            for (int j = 0; j < 4; j++) {
                int p0 = (wn * 4 + j) * 8 + 2 * tg;
#pragma unroll
                for (int e = 0; e < 2; e++) {
                    int p = p0 + e;
                    if (p < P) {
                        float v = (acc[i][j][half * 2 + e] + bi) * sc + sh;
                        if (MODE == 0) Ob[(long long)r * P + p] = fmaxf(v, 0.f);
                        else           atomicAdd(&Ob[(long long)r * P + p], fmaxf(v, 0.f));
                    }
                }
            }
        }
    }
}

// ================= BF16 3-term GEMM (lo-chain split-K) =================
// MODE 3: raw atomicAdd. XBN: BN+relu on X load.
template<int MODE, bool XBN>
__global__ __launch_bounds__(256) void tgemm(
    const float* __restrict__ W, const float* __restrict__ X,
    const float* __restrict__ bias, const float* __restrict__ gamma,
    const float* __restrict__ beta, float* __restrict__ out,
    const float* __restrict__ xb, const float* __restrict__ xg,
    const float* __restrict__ xbb,
    int Kd, int P, int kchunk, long long strideX, long long strideO)
{
    __shared__ __align__(16) unsigned Asm[2][2][MT][32][4];
    __shared__ __align__(16) unsigned Bsm[2][2][NT][32][2];

    const float rsc = rsqrtf(1.f + 1e-5f);
    const float* Xb = X + (long long)blockIdx.z * strideX;
    float* Ob = out + (long long)blockIdx.z * strideO;
    const int row0 = blockIdx.y * BM;
    const int k_begin = blockIdx.x * kchunk;

    const int tid = threadIdx.x, lane = tid & 31, warp = tid >> 5;
    const int g = lane >> 2, tg = lane & 3;
    const int wm = warp >> 2, wn = warp & 3;

    float acc[4][4][4];
#pragma unroll
    for (int i = 0; i < 4; i++)
#pragma unroll
        for (int j = 0; j < 4; j++)
#pragma unroll
            for (int e = 0; e < 4; e++) acc[i][j][e] = 0.f;

    const int nt_iters = kchunk / 16;

    {
        const int k = k_begin;
        const float* wr = W + (long long)(row0 + warp * 16 + g) * Kd + k + 2 * tg;
        float2 v00 = *(const float2*)wr;
        float2 v10 = *(const float2*)(wr + 8 * Kd);
        float2 v01 = *(const float2*)(wr + 8);
        float2 v11 = *(const float2*)(wr + 8 * Kd + 8);
        unsigned h, l;
        split_pack(v00.x, v00.y, h, l); Asm[0][0][warp][lane][0] = h; Asm[0][1][warp][lane][0] = l;
        split_pack(v10.x, v10.y, h, l); Asm[0][0][warp][lane][1] = h; Asm[0][1][warp][lane][1] = l;
        split_pack(v01.x, v01.y, h, l); Asm[0][0][warp][lane][2] = h; Asm[0][1][warp][lane][2] = l;
        split_pack(v11.x, v11.y, h, l); Asm[0][0][warp][lane][3] = h; Asm[0][1][warp][lane][3] = l;
#pragma unroll
        for (int q = 0; q < 2; q++) {
            int nt = warp * 2 + q;
            int p = nt * 8 + g;
            float b0a = 0.f, b0b = 0.f, b1a = 0.f, b1b = 0.f;
            if (p < P) {
                int k0 = k + 2 * tg;
                b0a = Xb[(long long)k0 * P + p];
                b0b = Xb[(long long)(k0 + 1) * P + p];
                b1a = Xb[(long long)(k0 + 8) * P + p];
                b1b = Xb[(long long)(k0 + 9) * P + p];
                if (XBN) {
                    b0a = fmaxf((b0a + xb[k0])     * (xg[k0]     * rsc) + xbb[k0], 0.f);
                    b0b = fmaxf((b0b + xb[k0 + 1]) * (xg[k0 + 1] * rsc) + xbb[k0 + 1], 0.f);
                    b1a = fmaxf((b1a + xb[k0 + 8]) * (xg[k0 + 8] * rsc) + xbb[k0 + 8], 0.f);
                    b1b = fmaxf((b1b + xb[k0 + 9]) * (xg[k0 + 9] * rsc) + xbb[k0 + 9], 0.f);
                }
            }
            unsigned h2, l2;
            split_pack(b0a, b0b, h2, l2); Bsm[0][0][nt][lane][0] = h2; Bsm[0][1][nt][lane][0] = l2;
            split_pack(b1a, b1b, h2, l2); Bsm[0][0][nt][lane][1] = h2; Bsm[0][1][nt][lane][1] = l2;
        }
    }
    __syncthreads();

    for (int t = 0; t < nt_iters; t++) {
        const int cur = t & 1;
        const bool has_next = (t + 1 < nt_iters);
        float2 v00, v01, v10, v11;
        float xv0[2][2], xv1[2][2];
        if (has_next) {
            const int k = k_begin + (t + 1) * 16;
            const float* wr = W + (long long)(row0 + warp * 16 + g) * Kd + k + 2 * tg;
            v00 = *(const float2*)wr;
            v10 = *(const float2*)(wr + 8 * Kd);
            v01 = *(const float2*)(wr + 8);
            v11 = *(const float2*)(wr + 8 * Kd + 8);
#pragma unroll
            for (int q = 0; q < 2; q++) {
                int nt = warp * 2 + q;
                int p = nt * 8 + g;
                xv0[q][0] = 0.f; xv0[q][1] = 0.f; xv1[q][0] = 0.f; xv1[q][1] = 0.f;
                if (p < P) {
                    int k0 = k + 2 * tg;
                    xv0[q][0] = Xb[(long long)k0 * P + p];
                    xv0[q][1] = Xb[(long long)(k0 + 1) * P + p];
                    xv1[q][0] = Xb[(long long)(k0 + 8) * P + p];
                    xv1[q][1] = Xb[(long long)(k0 + 9) * P + p];
                    if (XBN) {
                        xv0[q][0] = fmaxf((xv0[q][0] + xb[k0])     * (xg[k0]     * rsc) + xbb[k0], 0.f);
                        xv0[q][1] = fmaxf((xv0[q][1] + xb[k0 + 1]) * (xg[k0 + 1] * rsc) + xbb[k0 + 1], 0.f);
                        xv1[q][0] = fmaxf((xv1[q][0] + xb[k0 + 8]) * (xg[k0 + 8] * rsc) + xbb[k0 + 8], 0.f);
                        xv1[q][1] = fmaxf((xv1[q][1] + xb[k0 + 9]) * (xg[k0 + 9] * rsc) + xbb[k0 + 9], 0.f);
                    }
                }
            }
        }

        unsigned aF[2][4][4], bF[2][4][2];
#pragma unroll
        for (int s = 0; s < 2; s++)
#pragma unroll
            for (int i = 0; i < 4; i++) {
                uint4 a4 = *(const uint4*)&Asm[cur][s][wm * 4 + i][lane][0];
                aF[s][i][0] = a4.x; aF[s][i][1] = a4.y; aF[s][i][2] = a4.z; aF[s][i][3] = a4.w;
            }
#pragma unroll
        for (int s = 0; s < 2; s++)
#pragma unroll
            for (int j = 0; j < 4; j++) {
                uint2 b2 = *(const uint2*)&Bsm[cur][s][wn * 4 + j][lane][0];
                bF[s][j][0] = b2.x; bF[s][j][1] = b2.y;
            }

#pragma unroll
        for (int i = 0; i < 4; i++)
#pragma unroll
            for (int j = 0; j < 4; j++) {
                mma_bf16(acc[i][j], aF[0][i], bF[0][j]);
                mma_bf16(acc[i][j], aF[0][i], bF[1][j]);
                mma_bf16(acc[i][j], aF[1][i], bF[0][j]);
            }

        if (has_next) {
            const int nb = cur ^ 1;
            unsigned h, l;
            split_pack(v00.x, v00.y, h, l); Asm[nb][0][warp][lane][0] = h; Asm[nb][1][warp][lane][0] = l;
            split_pack(v10.x, v10.y, h, l); Asm[nb][0][warp][lane][1] = h; Asm[nb][1][warp][lane][1] = l;
            split_pack(v01.x, v01.y, h, l); Asm[nb][0][warp][lane][2] = h; Asm[nb][1][warp][lane][2] = l;
            split_pack(v11.x, v11.y, h, l); Asm[nb][0][warp][lane][3] = h; Asm[nb][1][warp][lane][3] = l;
#pragma unroll
            for (int q = 0; q < 2; q++) {
                int nt = warp * 2 + q;
                split_pack(xv0[q][0], xv0[q][1], h, l);
                Bsm[nb][0][nt][lane][0] = h; Bsm[nb][1][nt][lane][0] = l;
                split_pack(xv1[q][0], xv1[q][1], h, l);
                Bsm[nb][0][nt][lane][1] = h; Bsm[nb][1][nt][lane][1] = l;
            }
            __syncthreads();
        }
    }

#pragma unroll
    for (int i = 0; i < 4; i++) {
        int r0 = row0 + (wm * 4 + i) * 16 + g;
#pragma unroll
        for (int half = 0; half < 2; half++) {
            int r = r0 + half * 8;
#pragma unroll
            for (int j = 0; j < 4; j++) {
                int p0 = (wn * 4 + j) * 8 + 2 * tg;
#pragma unroll
                for (int e = 0; e < 2; e++) {
                    int p = p0 + e;
                    if (p < P) atomicAdd(&Ob[(long long)r * P + p], acc[i][j][half * 2 + e]);
                }
            }
        }
    }
}

// ---------------- fused zero fill ----------------
__global__ void zero_multi(float* p0, int n0, float* p1, int n1, float* p2, int n2,
                           float* p3, int n3, float* p4, int n4)
{
    int i = blockIdx.x * 256 + threadIdx.x;
    if (i < n0) { p0[i] = 0.f; return; }
    i -= n0;
    if (i < n1) { p1[i] = 0.f; return; }
    i -= n1;
    if (i < n2) { p2[i] = 0.f; return; }
    i -= n2;
    if (i < n3) { p3[i] = 0.f; return; }
    i -= n3;
    if (i < n4) p4[i] = 0.f;
}

// ---------------- split-K epilogue: BN + sigmoid ----------------
__global__ void epi_sig(const float* __restrict__ acc, const float* __restrict__ bias,
                        const float* __restrict__ gamma, const float* __restrict__ beta,
                        float* __restrict__ out, int P, int n)
{
    int i = blockIdx.x * 256 + threadIdx.x;
    if (i < n) {
        int r = i / P;
        float v = (acc[i] + bias[r]) * gamma[r] * rsqrtf(1.f + 1e-5f) + beta[r];
        out[i] = 1.f / (1.f + expf(-v));
    }
}

// ---------------- spatial kernel, split over channel chunks ----------------
__global__ __launch_bounds__(128) void spatial_part(
    const float* __restrict__ f, const float* __restrict__ w_conv,
    float* __restrict__ raw)
{
    __shared__ float wc[KK * 128];
    const int b = blockIdx.x;
    const int c0 = blockIdx.y * 128;
    const int tid = threadIdx.x;
    for (int i = tid; i < KK * 128; i += 128) {
        int k = i >> 7, cc = i & 127;
        wc[i] = w_conv[k * CCH + c0 + cc];
    }
    __syncthreads();
    if (tid < SS) {
        float acc[KK];
#pragma unroll
        for (int k = 0; k < KK; k++) acc[k] = 0.f;
        const float* fb = f + (long long)b * CCH * SS + (long long)c0 * SS;
        for (int cc = 0; cc < 128; cc++) {
            float xv = fb[cc * SS + tid];
#pragma unroll
            for (int k = 0; k < KK; k++) acc[k] = fmaf(xv, wc[k * 128 + cc], acc[k]);
        }
#pragma unroll
        for (int k = 0; k < KK; k++)
            atomicAdd(&raw[(long long)b * SS * KK + tid * KK + k], acc[k]);
    }
}

__global__ __launch_bounds__(128) void spatial_bn(
    const float* __restrict__ raw, const float* __restrict__ b_conv,
    const float* __restrict__ g_sp, const float* __restrict__ b_sp,
    float* __restrict__ out)
{
    const int b = blockIdx.x;
    const int tid = threadIdx.x;
    if (tid < SS) {
        float gs = g_sp[tid] * rsqrtf(1.f + 1e-5f);
        float bs = b_sp[tid];
#pragma unroll
        for (int k = 0; k < KK; k++) {
            long long idx = (long long)b * SS * KK + tid * KK + k;
            out[idx] = (raw[idx] + b_conv[k]) * gs + bs;
        }
    }
}

// ---------------- DCT pooling ----------------
__global__ __launch_bounds__(128) void dct_pool(
    const float* __restrict__ f, const float* __restrict__ dct, float* __restrict__ y)
{
    const int b = blockIdx.y;
    const int c = blockIdx.x * 4 + (threadIdx.x >> 5);
    const int lane = threadIdx.x & 31;
    const float* fb = f + ((long long)b * CCH + c) * SS;
    const float* dc = dct + (long long)c * SS;
    float s = 0.f;
    for (int p = lane; p < SS; p += 32) s = fmaf(fb[p], dc[p], s);
#pragma unroll
    for (int o = 16; o > 0; o >>= 1) s += __shfl_xor_sync(0xffffffffu, s, o);
    if (lane == 0) y[(long long)b * CCH + c] = s;
}

// ---------------- channel-attention MLP ----------------
__global__ __launch_bounds__(256) void mlp_k(
    const float* __restrict__ y, const float* __restrict__ fc1,
    const float* __restrict__ fc2, const float* __restrict__ g_ch,
    const float* __restrict__ b_ch, float* __restrict__ ck)
{
    __shared__ float ys[CCH];
    __shared__ float hs[CR];
    const int b = blockIdx.x;
    const int tid = threadIdx.x;
    for (int i = tid; i < CCH; i += 256) ys[i] = y[(long long)b * CCH + i];
    __syncthreads();
    if (tid < CR) {
        const float* r = fc1 + tid * CCH;
        float s = 0.f;
        for (int c = 0; c < CCH; c++) s = fmaf(ys[c], r[c], s);
        hs[tid] = fmaxf(s, 0.f);
    }
    __syncthreads();
    const float rs = rsqrtf(1.f + 1e-5f);
    for (int m = tid; m < CCH * KK; m += 256) {
        const float* r = fc2 + m * CR;
        float s = 0.f;
#pragma unroll
        for (int j = 0; j < CR; j++) s = fmaf(hs[j], r[j], s);
        s = 1.f / (1.f + expf(-s));
        int c = m / KK;
        ck[(long long)b * CCH * KK + m] = s * g_ch[c] * rs + b_ch[c];
    }
}

// ---------------- task kernel writer (off critical path, on s3) ----------------
__global__ __launch_bounds__(128) void tk_writer(
    const float* __restrict__ skt, const float* __restrict__ ckt, float* __restrict__ tk)
{
    const int c = blockIdx.x;
    for (int i = threadIdx.x; i < SS * KK; i += 128) {
        int kk = i % KK;
        tk[(long long)c * SS * KK + i] = skt[i] * ckt[c * KK + kk];
    }
}

// ---------------- final: adapted + x, computes tk inline ----------------
__global__ __launch_bounds__(128) void final_k2(
    const float* __restrict__ x, const float* __restrict__ sk,
    const float* __restrict__ ck, const float* __restrict__ skt,
    const float* __restrict__ ckt, float* __restrict__ out)
{
    __shared__ float xs[13 * 13];
    __shared__ float sks[SS * KK];
    const int c0 = blockIdx.x * 8, b = blockIdx.y;
    const int tid = threadIdx.x;

    for (int i = tid; i < 169; i += 128) xs[i] = 0.f;
    for (int i = tid; i < SS * KK; i += 128)
        sks[i] = sk[(long long)b * SS * KK + i] * skt[i];
    __syncthreads();

    const int p = tid;
    const int h = p / SDIM, w = p % SDIM;

    for (int cg = 0; cg < 8; cg++) {
        const int c = c0 + cg;
        const float* xb = x + ((long long)b * CCH + c) * SS;
        if (p < SS) xs[(h + 1) * 13 + (w + 1)] = xb[p];
        __syncthreads();
        if (p < SS) {
            float ckv[KK];
#pragma unroll
            for (int k = 0; k < KK; k++)
                ckv[k] = ck[((long long)b * CCH + c) * KK + k] * ckt[c * KK + k];
            float acc = 0.f;
#pragma unroll
            for (int k = 0; k < KK; k++) {
                int ki = k / 3, kj = k % 3;
                float xv = xs[(h + ki) * 13 + (w + kj)];
                acc = fmaf(xv, sks[p * KK + k] * ckv[k], acc);
            }
            out[((long long)b * CCH + c) * SS + p] = acc * (1.f / 9.f) + xb[p];
        }
        __syncthreads();
    }
}

// ---------------- launch ----------------
extern "C" void kernel_launch(void* const* d_in, const int* in_sizes, int n_in,
                              void* d_out, int out_size)
{
    const float* x      = (const float*)d_in[0];
    const float* dct_w  = (const float*)d_in[1];
    const float* w_conv = (const float*)d_in[2];
    const float* b_conv = (const float*)d_in[3];
    const float* g_sp   = (const float*)d_in[4];
    const float* b_sp   = (const float*)d_in[5];
    const float* g_ch   = (const float*)d_in[6];
    const float* b_ch   = (const float*)d_in[7];
    const float* fc1    = (const float*)d_in[8];
    const float* fc2    = (const float*)d_in[9];
    const float* up_w1  = (const float*)d_in[10];
    const float* up_b1  = (const float*)d_in[11];
    const float* up_g1  = (const float*)d_in[12];
    const float* up_bb1 = (const float*)d_in[13];
    const float* up_w2  = (const float*)d_in[14];
    const float* up_b2  = (const float*)d_in[15];
    const float* up_g2  = (const float*)d_in[16];
    const float* up_bb2 = (const float*)d_in[17];
    const float* lo_w1  = (const float*)d_in[18];
    const float* lo_b1  = (const float*)d_in[19];
    const float* lo_g1  = (const float*)d_in[20];
    const float* lo_bb1 = (const float*)d_in[21];
    const float* lo_w2  = (const float*)d_in[22];
    const float* lo_b2  = (const float*)d_in[23];
    const float* lo_g2  = (const float*)d_in[24];
    const float* lo_bb2 = (const float*)d_in[25];

    float *A1, *asum, *acc1, *acc2, *task;
    float *sk, *skraw, *skt, *sktraw, *y, *yt, *ck, *ckt;
    cudaGetSymbolAddress((void**)&A1,     g_A1);
    cudaGetSymbolAddress((void**)&asum,   g_asum);
    cudaGetSymbolAddress((void**)&acc1,   g_acc1);
    cudaGetSymbolAddress((void**)&acc2,   g_acc2);
    cudaGetSymbolAddress((void**)&task,   g_task);
    cudaGetSymbolAddress((void**)&sk,     g_sk);
    cudaGetSymbolAddress((void**)&skraw,  g_skraw);
    cudaGetSymbolAddress((void**)&skt,    g_skt);
    cudaGetSymbolAddress((void**)&sktraw, g_sktraw);
    cudaGetSymbolAddress((void**)&y,      g_y);
    cudaGetSymbolAddress((void**)&yt,     g_yt);
    cudaGetSymbolAddress((void**)&ck,     g_ck);
    cudaGetSymbolAddress((void**)&ckt,    g_ckt);

    float* out = (float*)d_out;
    float* tk  = out + OUT0;

    static cudaStream_t s2 = nullptr, s3 = nullptr;
    static cudaEvent_t ev_fork = nullptr, ev_join = nullptr;
    static cudaEvent_t ev_tk = nullptr, ev_tkdone = nullptr;
    if (!s2) {
        cudaStreamCreate(&s2);
        cudaStreamCreate(&s3);
        cudaEventCreateWithFlags(&ev_fork, cudaEventDisableTiming);
        cudaEventCreateWithFlags(&ev_join, cudaEventDisableTiming);
        cudaEventCreateWithFlags(&ev_tk, cudaEventDisableTiming);
        cudaEventCreateWithFlags(&ev_tkdone, cudaEventDisableTiming);
    }

    // zero accumulators in one launch (main stream)
    {
        int n0 = C2 * SS, n1 = C2 * SS, n2 = CCH * SS;
        int n3 = BATCH * SS * KK, n4 = SS * KK;
        int ntot = n0 + n1 + n2 + n3 + n4;
        zero_multi<<<(ntot + 255) / 256, 256>>>(asum, n0, acc1, n1, acc2, n2,
                                                skraw, n3, sktraw, n4);
    }

    // fork: instance path runs concurrently with the GEMM chain
    cudaEventRecord(ev_fork, 0);
    cudaStreamWaitEvent(s2, ev_fork, 0);
    spatial_part<<<dim3(BATCH, CCH / 128), 128, 0, s2>>>(x, w_conv, skraw);
    spatial_bn<<<BATCH, 128, 0, s2>>>(skraw, b_conv, g_sp, b_sp, sk);
    dct_pool<<<dim3(CCH / 4, BATCH), 128, 0, s2>>>(x, dct_w, y);
    mlp_k<<<BATCH, 256, 0, s2>>>(y, fc1, fc2, g_ch, b_ch, ck);
    cudaEventRecord(ev_join, s2);

    // CLM task path: big GEMMs on fp16 2-term split
    tgemm_h<0><<<dim3(1, C2 / BM, BATCH), 256>>>(
        up_w1, x, up_b1, up_g1, up_bb1, A1,
        CCH, SS, (long long)CCH * SS, (long long)C2 * SS);
    tgemm_h<1><<<dim3(1, C2 / BM, BATCH), 256>>>(
        up_w2, A1, up_b2, up_g2, up_bb2, asum,
        C2, SS, (long long)C2 * SS, 0);
    // lo-chain: bf16 3-term split-K 32
    tgemm<3, false><<<dim3(32, C2 / BM, 1), 256>>>(
        lo_w1, asum, nullptr, nullptr, nullptr, acc1, nullptr, nullptr, nullptr,
        C2, SS, C2 / 32, 0, 0);
    tgemm<3, true><<<dim3(32, CCH / BM, 1), 256>>>(
        lo_w2, acc1, nullptr, nullptr, nullptr, acc2, lo_b1, lo_g1, lo_bb1,
        C2, SS, C2 / 32, 0, 0);
    epi_sig<<<(CCH * SS + 255) / 256, 256>>>(acc2, lo_b2, lo_g2, lo_bb2, task, SS, CCH * SS);

    // task-path small kernels (main stream)
    spatial_part<<<dim3(1, CCH / 128), 128>>>(task, w_conv, sktraw);
    spatial_bn<<<1, 128>>>(sktraw, b_conv, g_sp, b_sp, skt);
    dct_pool<<<dim3(CCH / 4, 1), 128>>>(task, dct_w, yt);
    mlp_k<<<1, 256>>>(yt, fc1, fc2, g_ch, b_ch, ckt);

    // tk_writer off critical path on s3
    cudaEventRecord(ev_tk, 0);
    cudaStreamWaitEvent(s3, ev_tk, 0);
    tk_writer<<<CCH, 128, 0, s3>>>(skt, ckt, tk);
    cudaEventRecord(ev_tkdone, s3);

    // final: needs sk/ck (s2) + skt/ckt (main); computes tk inline
    cudaStreamWaitEvent(0, ev_join, 0);
    final_k2<<<dim3(CCH / 8, BATCH), 128>>>(x, sk, ck, skt, ckt, out);

    cudaStreamWaitEvent(0, ev_tkdone, 0);
}

// round 15
// speedup vs baseline: 1.1106x; 1.1106x over previous
#include <cuda_runtime.h>
#include <cuda_bf16.h>
#include <math.h>

// ---------------- problem constants ----------------
#define BATCH 128
#define CCH   512
#define SS    121      // 11*11
#define SDIM  11
#define KK    9        // 3*3
#define C2    1024     // 2*C
#define CR    32       // C/SIGMA
#define OUT0  (BATCH*CCH*SS)

// ---------------- scratch (device globals; no allocation) ----------------
__device__ float g_A1[(size_t)BATCH * C2 * SS];
__device__ float g_asum[C2 * SS];
__device__ float g_acc1[C2 * SS];
__device__ float g_acc2[CCH * SS];
__device__ float g_task[CCH * SS];
__device__ float g_sk[BATCH * SS * KK];
__device__ float g_skraw[BATCH * SS * KK];
__device__ float g_skt[SS * KK];
__device__ float g_sktraw[SS * KK];
__device__ float g_y[BATCH * CCH];
__device__ float g_yt[CCH];
__device__ float g_ck[(size_t)BATCH * CCH * KK];
__device__ float g_ckt[CCH * KK];

// ---------------- bf16 split helpers ----------------
__device__ __forceinline__ void split_pack(float a, float b, unsigned& hi, unsigned& lo) {
    __nv_bfloat162 h = __float22bfloat162_rn(make_float2(a, b));
    float ra = a - __bfloat162float(h.x);
    float rb = b - __bfloat162float(h.y);
    __nv_bfloat162 l = __float22bfloat162_rn(make_float2(ra, rb));
    hi = *(unsigned*)&h;
    lo = *(unsigned*)&l;
}

__device__ __forceinline__ void mma_bf16(float c[4], const unsigned a[4], const unsigned b[2]) {
    asm volatile(
        "mma.sync.aligned.m16n8k16.row.col.f32.bf16.bf16.f32 "
        "{%0,%1,%2,%3}, {%4,%5,%6,%7}, {%8,%9}, {%0,%1,%2,%3};"
        : "+f"(c[0]), "+f"(c[1]), "+f"(c[2]), "+f"(c[3])
        : "r"(a[0]), "r"(a[1]), "r"(a[2]), "r"(a[3]), "r"(b[0]), "r"(b[1]));
}

// ================= tensor-core GEMM (3xBF16 split), 128x128 tile, BK=16 =================
// O[o][p] = act( (sum_c W[o][c]*X[c][p] + bias[o]) * gamma[o]/sqrt(1+eps) + beta[o] )
// MODE 0: BN+relu store; MODE 1: BN+relu atomicAdd (batch reduce);
// MODE 3: raw atomicAdd (split-K partial, no BN)
// XBN: transform X on load: x = relu((x + xb[k])*xg[k]/sqrt(1+eps) + xbb[k])
#define BM 128
#define MT 8
#define NT 16

template<int MODE, bool XBN>
__global__ __launch_bounds__(256) void tgemm(
    const float* __restrict__ W, const float* __restrict__ X,
    const float* __restrict__ bias, const float* __restrict__ gamma,
    const float* __restrict__ beta, float* __restrict__ out,
    const float* __restrict__ xb, const float* __restrict__ xg,
    const float* __restrict__ xbb,
    int Kd, int P, int kchunk, long long strideX, long long strideO)
{
    __shared__ __align__(16) unsigned Asm[2][2][MT][32][4];
    __shared__ __align__(16) unsigned Bsm[2][2][NT][32][2];

    const float rsc = rsqrtf(1.f + 1e-5f);
    const float* Xb = X + (long long)blockIdx.z * strideX;
    float* Ob = out + (long long)blockIdx.z * strideO;
    const int row0 = blockIdx.y * BM;
    const int k_begin = blockIdx.x * kchunk;

    const int tid = threadIdx.x, lane = tid & 31, warp = tid >> 5;
    const int g = lane >> 2, tg = lane & 3;
    const int wm = warp >> 2;   // 0..1
    const int wn = warp & 3;    // 0..3

    float acc[4][4][4];
#pragma unroll
    for (int i = 0; i < 4; i++)
#pragma unroll
        for (int j = 0; j < 4; j++)
#pragma unroll
            for (int e = 0; e < 4; e++) acc[i][j][e] = 0.f;

    const int nt_iters = kchunk / 16;

    // ---- prologue: stage 0 ----
    {
        const int k = k_begin;
        const float* wr = W + (long long)(row0 + warp * 16 + g) * Kd + k + 2 * tg;
        float2 v00 = *(const float2*)wr;
        float2 v10 = *(const float2*)(wr + 8 * Kd);
        float2 v01 = *(const float2*)(wr + 8);
        float2 v11 = *(const float2*)(wr + 8 * Kd + 8);
        unsigned h, l;
        split_pack(v00.x, v00.y, h, l); Asm[0][0][warp][lane][0] = h; Asm[0][1][warp][lane][0] = l;
        split_pack(v10.x, v10.y, h, l); Asm[0][0][warp][lane][1] = h; Asm[0][1][warp][lane][1] = l;
        split_pack(v01.x, v01.y, h, l); Asm[0][0][warp][lane][2] = h; Asm[0][1][warp][lane][2] = l;
        split_pack(v11.x, v11.y, h, l); Asm[0][0][warp][lane][3] = h; Asm[0][1][warp][lane][3] = l;
#pragma unroll
        for (int q = 0; q < 2; q++) {
            int nt = warp * 2 + q;
            int p = nt * 8 + g;
            float b0a = 0.f, b0b = 0.f, b1a = 0.f, b1b = 0.f;
            if (p < P) {
                int k0 = k + 2 * tg;
                b0a = Xb[(long long)k0 * P + p];
                b0b = Xb[(long long)(k0 + 1) * P + p];
                b1a = Xb[(long long)(k0 + 8) * P + p];
                b1b = Xb[(long long)(k0 + 9) * P + p];
                if (XBN) {
                    b0a = fmaxf((b0a + xb[k0])     * (xg[k0]     * rsc) + xbb[k0], 0.f);
                    b0b = fmaxf((b0b + xb[k0 + 1]) * (xg[k0 + 1] * rsc) + xbb[k0 + 1], 0.f);
                    b1a = fmaxf((b1a + xb[k0 + 8]) * (xg[k0 + 8] * rsc) + xbb[k0 + 8], 0.f);
                    b1b = fmaxf((b1b + xb[k0 + 9]) * (xg[k0 + 9] * rsc) + xbb[k0 + 9], 0.f);
                }
            }
            unsigned h2, l2;
            split_pack(b0a, b0b, h2, l2); Bsm[0][0][nt][lane][0] = h2; Bsm[0][1][nt][lane][0] = l2;
            split_pack(b1a, b1b, h2, l2); Bsm[0][0][nt][lane][1] = h2; Bsm[0][1][nt][lane][1] = l2;
        }
    }
    __syncthreads();

    for (int t = 0; t < nt_iters; t++) {
        const int cur = t & 1;
        const bool has_next = (t + 1 < nt_iters);
        float2 v00, v01, v10, v11;
        float xv0[2][2], xv1[2][2];
        if (has_next) {
            const int k = k_begin + (t + 1) * 16;
            const float* wr = W + (long long)(row0 + warp * 16 + g) * Kd + k + 2 * tg;
            v00 = *(const float2*)wr;
            v10 = *(const float2*)(wr + 8 * Kd);
            v01 = *(const float2*)(wr + 8);
            v11 = *(const float2*)(wr + 8 * Kd + 8);
#pragma unroll
            for (int q = 0; q < 2; q++) {
                int nt = warp * 2 + q;
                int p = nt * 8 + g;
                xv0[q][0] = 0.f; xv0[q][1] = 0.f; xv1[q][0] = 0.f; xv1[q][1] = 0.f;
                if (p < P) {
                    int k0 = k + 2 * tg;
                    xv0[q][0] = Xb[(long long)k0 * P + p];
                    xv0[q][1] = Xb[(long long)(k0 + 1) * P + p];
                    xv1[q][0] = Xb[(long long)(k0 + 8) * P + p];
                    xv1[q][1] = Xb[(long long)(k0 + 9) * P + p];
                    if (XBN) {
                        xv0[q][0] = fmaxf((xv0[q][0] + xb[k0])     * (xg[k0]     * rsc) + xbb[k0], 0.f);
                        xv0[q][1] = fmaxf((xv0[q][1] + xb[k0 + 1]) * (xg[k0 + 1] * rsc) + xbb[k0 + 1], 0.f);
                        xv1[q][0] = fmaxf((xv1[q][0] + xb[k0 + 8]) * (xg[k0 + 8] * rsc) + xbb[k0 + 8], 0.f);
                        xv1[q][1] = fmaxf((xv1[q][1] + xb[k0 + 9]) * (xg[k0 + 9] * rsc) + xbb[k0 + 9], 0.f);
                    }
                }
            }
        }

        unsigned aF[2][4][4], bF[2][4][2];
#pragma unroll
        for (int s = 0; s < 2; s++)
#pragma unroll
            for (int i = 0; i < 4; i++) {
                uint4 a4 = *(const uint4*)&Asm[cur][s][wm * 4 + i][lane][0];
                aF[s][i][0] = a4.x; aF[s][i][1] = a4.y; aF[s][i][2] = a4.z; aF[s][i][3] = a4.w;
            }
#pragma unroll
        for (int s = 0; s < 2; s++)
#pragma unroll
            for (int j = 0; j < 4; j++) {
                uint2 b2 = *(const uint2*)&Bsm[cur][s][wn * 4 + j][lane][0];
                bF[s][j][0] = b2.x; bF[s][j][1] = b2.y;
            }

#pragma unroll
        for (int i = 0; i < 4; i++)
#pragma unroll
            for (int j = 0; j < 4; j++) {
                mma_bf16(acc[i][j], aF[0][i], bF[0][j]);
                mma_bf16(acc[i][j], aF[0][i], bF[1][j]);
                mma_bf16(acc[i][j], aF[1][i], bF[0][j]);
            }

        if (has_next) {
            const int nb = cur ^ 1;
            unsigned h, l;
            split_pack(v00.x, v00.y, h, l); Asm[nb][0][warp][lane][0] = h; Asm[nb][1][warp][lane][0] = l;
            split_pack(v10.x, v10.y, h, l); Asm[nb][0][warp][lane][1] = h; Asm[nb][1][warp][lane][1] = l;
            split_pack(v01.x, v01.y, h, l); Asm[nb][0][warp][lane][2] = h; Asm[nb][1][warp][lane][2] = l;
            split_pack(v11.x, v11.y, h, l); Asm[nb][0][warp][lane][3] = h; Asm[nb][1][warp][lane][3] = l;
#pragma unroll
            for (int q = 0; q < 2; q++) {
                int nt = warp * 2 + q;
                split_pack(xv0[q][0], xv0[q][1], h, l);
                Bsm[nb][0][nt][lane][0] = h; Bsm[nb][1][nt][lane][0] = l;
                split_pack(xv1[q][0], xv1[q][1], h, l);
                Bsm[nb][0][nt][lane][1] = h; Bsm[nb][1][nt][lane][1] = l;
            }
            __syncthreads();
        }
    }

    // ---- epilogue ----
#pragma unroll
    for (int i = 0; i < 4; i++) {
        int r0 = row0 + (wm * 4 + i) * 16 + g;
#pragma unroll
        for (int half = 0; half < 2; half++) {
            int r = r0 + half * 8;
            float sc = 0.f, sh = 0.f, bi = 0.f;
            if (MODE != 3) { sc = gamma[r] * rsc; sh = beta[r]; bi = bias[r]; }
#pragma unroll
            for (int j = 0; j < 4; j++) {
                int p0 = (wn * 4 + j) * 8 + 2 * tg;
#pragma unroll
                for (int e = 0; e < 2; e++) {
                    int p = p0 + e;
                    if (p < P) {
                        float raw = acc[i][j][half * 2 + e];
                        if (MODE == 3) {
                            atomicAdd(&Ob[(long long)r * P + p], raw);
                        } else {
                            float v = (raw + bi) * sc + sh;
                            if (MODE == 0)      Ob[(long long)r * P + p] = fmaxf(v, 0.f);
                            else                atomicAdd(&Ob[(long long)r * P + p], fmaxf(v, 0.f));
                        }
                    }
                }
            }
        }
    }
}

// ---------------- fused zero fill ----------------
__global__ void zero_multi(float* p0, int n0, float* p1, int n1, float* p2, int n2,
                           float* p3, int n3, float* p4, int n4)
{
    int i = blockIdx.x * 256 + threadIdx.x;
    if (i < n0) { p0[i] = 0.f; return; }
    i -= n0;
    if (i < n1) { p1[i] = 0.f; return; }
    i -= n1;
    if (i < n2) { p2[i] = 0.f; return; }
    i -= n2;
    if (i < n3) { p3[i] = 0.f; return; }
    i -= n3;
    if (i < n4) p4[i] = 0.f;
}

// ---------------- split-K epilogue: BN + sigmoid ----------------
__global__ void epi_sig(const float* __restrict__ acc, const float* __restrict__ bias,
                        const float* __restrict__ gamma, const float* __restrict__ beta,
                        float* __restrict__ out, int P, int n)
{
    int i = blockIdx.x * 256 + threadIdx.x;
    if (i < n) {
        int r = i / P;
        float v = (acc[i] + bias[r]) * gamma[r] * rsqrtf(1.f + 1e-5f) + beta[r];
        out[i] = 1.f / (1.f + expf(-v));
    }
}

// ---------------- spatial kernel, split over channel chunks ----------------
__global__ __launch_bounds__(128) void spatial_part(
    const float* __restrict__ f, const float* __restrict__ w_conv,
    float* __restrict__ raw)
{
    __shared__ float wc[KK * 128];
    const int b = blockIdx.x;
    const int c0 = blockIdx.y * 128;
    const int tid = threadIdx.x;
    for (int i = tid; i < KK * 128; i += 128) {
        int k = i >> 7, cc = i & 127;
        wc[i] = w_conv[k * CCH + c0 + cc];
    }
    __syncthreads();
    if (tid < SS) {
        float acc[KK];
#pragma unroll
        for (int k = 0; k < KK; k++) acc[k] = 0.f;
        const float* fb = f + (long long)b * CCH * SS + (long long)c0 * SS;
        for (int cc = 0; cc < 128; cc++) {
            float xv = fb[cc * SS + tid];
#pragma unroll
            for (int k = 0; k < KK; k++) acc[k] = fmaf(xv, wc[k * 128 + cc], acc[k]);
        }
#pragma unroll
        for (int k = 0; k < KK; k++)
            atomicAdd(&raw[(long long)b * SS * KK + tid * KK + k], acc[k]);
    }
}

__global__ __launch_bounds__(128) void spatial_bn(
    const float* __restrict__ raw, const float* __restrict__ b_conv,
    const float* __restrict__ g_sp, const float* __restrict__ b_sp,
    float* __restrict__ out)
{
    const int b = blockIdx.x;
    const int tid = threadIdx.x;
    if (tid < SS) {
        float gs = g_sp[tid] * rsqrtf(1.f + 1e-5f);
        float bs = b_sp[tid];
#pragma unroll
        for (int k = 0; k < KK; k++) {
            long long idx = (long long)b * SS * KK + tid * KK + k;
            out[idx] = (raw[idx] + b_conv[k]) * gs + bs;
        }
    }
}

// ---------------- DCT pooling ----------------
__global__ __launch_bounds__(128) void dct_pool(
    const float* __restrict__ f, const float* __restrict__ dct, float* __restrict__ y)
{
    const int b = blockIdx.y;
    const int c = blockIdx.x * 4 + (threadIdx.x >> 5);
    const int lane = threadIdx.x & 31;
    const float* fb = f + ((long long)b * CCH + c) * SS;
    const float* dc = dct + (long long)c * SS;
    float s = 0.f;
    for (int p = lane; p < SS; p += 32) s = fmaf(fb[p], dc[p], s);
#pragma unroll
    for (int o = 16; o > 0; o >>= 1) s += __shfl_xor_sync(0xffffffffu, s, o);
    if (lane == 0) y[(long long)b * CCH + c] = s;
}

// ---------------- channel-attention MLP ----------------
__global__ __launch_bounds__(256) void mlp_k(
    const float* __restrict__ y, const float* __restrict__ fc1,
    const float* __restrict__ fc2, const float* __restrict__ g_ch,
    const float* __restrict__ b_ch, float* __restrict__ ck)
{
    __shared__ float ys[CCH];
    __shared__ float hs[CR];
    const int b = blockIdx.x;
    const int tid = threadIdx.x;
    for (int i = tid; i < CCH; i += 256) ys[i] = y[(long long)b * CCH + i];
    __syncthreads();
    if (tid < CR) {
        const float* r = fc1 + tid * CCH;
        float s = 0.f;
        for (int c = 0; c < CCH; c++) s = fmaf(ys[c], r[c], s);
        hs[tid] = fmaxf(s, 0.f);
    }
    __syncthreads();
    const float rs = rsqrtf(1.f + 1e-5f);
    for (int m = tid; m < CCH * KK; m += 256) {
        const float* r = fc2 + m * CR;
        float s = 0.f;
#pragma unroll
        for (int j = 0; j < CR; j++) s = fmaf(hs[j], r[j], s);
        s = 1.f / (1.f + expf(-s));
        int c = m / KK;
        ck[(long long)b * CCH * KK + m] = s * g_ch[c] * rs + b_ch[c];
    }
}

// ---------------- task kernel writer (off critical path, on s3) ----------------
__global__ __launch_bounds__(128) void tk_writer(
    const float* __restrict__ skt, const float* __restrict__ ckt, float* __restrict__ tk)
{
    const int c = blockIdx.x;
    for (int i = threadIdx.x; i < SS * KK; i += 128) {
        int kk = i % KK;
        tk[(long long)c * SS * KK + i] = skt[i] * ckt[c * KK + kk];
    }
}

// ---------------- final: adapted + x, computes tk inline ----------------
__global__ __launch_bounds__(128) void final_k2(
    const float* __restrict__ x, const float* __restrict__ sk,
    const float* __restrict__ ck, const float* __restrict__ skt,
    const float* __restrict__ ckt, float* __restrict__ out)
{
    __shared__ float xs[13 * 13];
    __shared__ float sks[SS * KK];
    const int c0 = blockIdx.x * 8, b = blockIdx.y;
    const int tid = threadIdx.x;

    for (int i = tid; i < 169; i += 128) xs[i] = 0.f;
    for (int i = tid; i < SS * KK; i += 128)
        sks[i] = sk[(long long)b * SS * KK + i] * skt[i];
    __syncthreads();

    const int p = tid;
    const int h = p / SDIM, w = p % SDIM;

    for (int cg = 0; cg < 8; cg++) {
        const int c = c0 + cg;
        const float* xb = x + ((long long)b * CCH + c) * SS;
        float xcenter = 0.f;
        if (p < SS) {
            xcenter = xb[p];
            xs[(h + 1) * 13 + (w + 1)] = xcenter;
        }
        __syncthreads();
        if (p < SS) {
            float ckv[KK];
#pragma unroll
            for (int k = 0; k < KK; k++)
                ckv[k] = ck[((long long)b * CCH + c) * KK + k] * ckt[c * KK + k];
            float acc = 0.f;
#pragma unroll
            for (int k = 0; k < KK; k++) {
                int ki = k / 3, kj = k % 3;
                float xv = xs[(h + ki) * 13 + (w + kj)];
                acc = fmaf(xv, sks[p * KK + k] * ckv[k], acc);
            }
            out[((long long)b * CCH + c) * SS + p] = acc * (1.f / 9.f) + xcenter;
        }
        __syncthreads();
    }
}

// ---------------- launch ----------------
extern "C" void kernel_launch(void* const* d_in, const int* in_sizes, int n_in,
                              void* d_out, int out_size)
{
    const float* x      = (const float*)d_in[0];
    const float* dct_w  = (const float*)d_in[1];
    const float* w_conv = (const float*)d_in[2];
    const float* b_conv = (const float*)d_in[3];
    const float* g_sp   = (const float*)d_in[4];
    const float* b_sp   = (const float*)d_in[5];
    const float* g_ch   = (const float*)d_in[6];
    const float* b_ch   = (const float*)d_in[7];
    const float* fc1    = (const float*)d_in[8];
    const float* fc2    = (const float*)d_in[9];
    const float* up_w1  = (const float*)d_in[10];
    const float* up_b1  = (const float*)d_in[11];
    const float* up_g1  = (const float*)d_in[12];
    const float* up_bb1 = (const float*)d_in[13];
    const float* up_w2  = (const float*)d_in[14];
    const float* up_b2  = (const float*)d_in[15];
    const float* up_g2  = (const float*)d_in[16];
    const float* up_bb2 = (const float*)d_in[17];
    const float* lo_w1  = (const float*)d_in[18];
    const float* lo_b1  = (const float*)d_in[19];
    const float* lo_g1  = (const float*)d_in[20];
    const float* lo_bb1 = (const float*)d_in[21];
    const float* lo_w2  = (const float*)d_in[22];
    const float* lo_b2  = (const float*)d_in[23];
    const float* lo_g2  = (const float*)d_in[24];
    const float* lo_bb2 = (const float*)d_in[25];

    float *A1, *asum, *acc1, *acc2, *task;
    float *sk, *skraw, *skt, *sktraw, *y, *yt, *ck, *ckt;
    cudaGetSymbolAddress((void**)&A1,     g_A1);
    cudaGetSymbolAddress((void**)&asum,   g_asum);
    cudaGetSymbolAddress((void**)&acc1,   g_acc1);
    cudaGetSymbolAddress((void**)&acc2,   g_acc2);
    cudaGetSymbolAddress((void**)&task,   g_task);
    cudaGetSymbolAddress((void**)&sk,     g_sk);
    cudaGetSymbolAddress((void**)&skraw,  g_skraw);
    cudaGetSymbolAddress((void**)&skt,    g_skt);
    cudaGetSymbolAddress((void**)&sktraw, g_sktraw);
    cudaGetSymbolAddress((void**)&y,      g_y);
    cudaGetSymbolAddress((void**)&yt,     g_yt);
    cudaGetSymbolAddress((void**)&ck,     g_ck);
    cudaGetSymbolAddress((void**)&ckt,    g_ckt);

    float* out = (float*)d_out;
    float* tk  = out + OUT0;

    static cudaStream_t s2 = nullptr, s3 = nullptr;
    static cudaEvent_t ev_fork = nullptr, ev_join = nullptr;
    static cudaEvent_t ev_sig = nullptr, ev_skt = nullptr;
    static cudaEvent_t ev_ckt = nullptr, ev_tkdone = nullptr;
    if (!s2) {
        cudaStreamCreate(&s2);
        cudaStreamCreate(&s3);
        cudaEventCreateWithFlags(&ev_fork, cudaEventDisableTiming);
        cudaEventCreateWithFlags(&ev_join, cudaEventDisableTiming);
        cudaEventCreateWithFlags(&ev_sig, cudaEventDisableTiming);
        cudaEventCreateWithFlags(&ev_skt, cudaEventDisableTiming);
        cudaEventCreateWithFlags(&ev_ckt, cudaEventDisableTiming);
        cudaEventCreateWithFlags(&ev_tkdone, cudaEventDisableTiming);
    }

    // zero accumulators in one launch (main stream)
    {
        int n0 = C2 * SS, n1 = C2 * SS, n2 = CCH * SS;
        int n3 = BATCH * SS * KK, n4 = SS * KK;
        int ntot = n0 + n1 + n2 + n3 + n4;
        zero_multi<<<(ntot + 255) / 256, 256>>>(asum, n0, acc1, n1, acc2, n2,
                                                skraw, n3, sktraw, n4);
    }

    // fork: instance path runs concurrently with the GEMM chain
    cudaEventRecord(ev_fork, 0);
    cudaStreamWaitEvent(s2, ev_fork, 0);
    spatial_part<<<dim3(BATCH, CCH / 128), 128, 0, s2>>>(x, w_conv, skraw);
    spatial_bn<<<BATCH, 128, 0, s2>>>(skraw, b_conv, g_sp, b_sp, sk);
    dct_pool<<<dim3(CCH / 4, BATCH), 128, 0, s2>>>(x, dct_w, y);
    mlp_k<<<BATCH, 256, 0, s2>>>(y, fc1, fc2, g_ch, b_ch, ck);
    cudaEventRecord(ev_join, s2);

    // CLM task path (main stream) — bf16 3-term GEMMs (proven champion config)
    tgemm<0, false><<<dim3(1, C2 / BM, BATCH), 256>>>(
        up_w1, x, up_b1, up_g1, up_bb1, A1, nullptr, nullptr, nullptr,
        CCH, SS, CCH, (long long)CCH * SS, (long long)C2 * SS);
    tgemm<1, false><<<dim3(1, C2 / BM, BATCH), 256>>>(
        up_w2, A1, up_b2, up_g2, up_bb2, asum, nullptr, nullptr, nullptr,
        C2, SS, C2, (long long)C2 * SS, 0);
    // lo-chain: split-K 32
    tgemm<3, false><<<dim3(32, C2 / BM, 1), 256>>>(
        lo_w1, asum, nullptr, nullptr, nullptr, acc1, nullptr, nullptr, nullptr,
        C2, SS, C2 / 32, 0, 0);
    tgemm<3, true><<<dim3(32, CCH / BM, 1), 256>>>(
        lo_w2, acc1, nullptr, nullptr, nullptr, acc2, lo_b1, lo_g1, lo_bb1,
        C2, SS, C2 / 32, 0, 0);
    epi_sig<<<(CCH * SS + 255) / 256, 256>>>(acc2, lo_b2, lo_g2, lo_bb2, task, SS, CCH * SS);
    cudaEventRecord(ev_sig, 0);

    // task-path tail: two independent chains, overlapped
    //   main: spatial_part -> spatial_bn  (produces skt)
    //   s3:   dct_pool -> mlp_k           (produces ckt), then tk_writer
    cudaStreamWaitEvent(s3, ev_sig, 0);
    spatial_part<<<dim3(1, CCH / 128), 128>>>(task, w_conv, sktraw);
    spatial_bn<<<1, 128>>>(sktraw, b_conv, g_sp, b_sp, skt);
    cudaEventRecord(ev_skt, 0);
    dct_pool<<<dim3(CCH / 4, 1), 128, 0, s3>>>(task, dct_w, yt);
    mlp_k<<<1, 256, 0, s3>>>(yt, fc1, fc2, g_ch, b_ch, ckt);
    cudaEventRecord(ev_ckt, s3);
    cudaStreamWaitEvent(s3, ev_skt, 0);
    tk_writer<<<CCH, 128, 0, s3>>>(skt, ckt, tk);
    cudaEventRecord(ev_tkdone, s3);

    // final: needs sk/ck (s2) + skt (main) + ckt (s3); computes tk inline
    cudaStreamWaitEvent(0, ev_join, 0);
    cudaStreamWaitEvent(0, ev_ckt, 0);
    final_k2<<<dim3(CCH / 8, BATCH), 128>>>(x, sk, ck, skt, ckt, out);

    cudaStreamWaitEvent(0, ev_tkdone, 0);
}